// round 1
// baseline (speedup 1.0000x reference)
#include <cuda_runtime.h>
#include <cuda_bf16.h>
#include <cstdint>
#include <cstddef>

// Problem constants
#define BATCH   4
#define N1      4096
#define N2      4096
#define DIM     256      // input feature dim == HIDDEN
#define HID     256
#define ROWS_Q  (BATCH * N1)   // 16384
#define ROWS_K  (BATCH * N2)   // 16384

// GEMM tiling
#define BM 128
#define BN 128
#define BKK 16
#define PAD 4

// Scratch (device globals: allocation-free per harness rules)
__device__ float g_Q[(size_t)ROWS_Q * HID];
__device__ float g_K[(size_t)ROWS_K * HID];
__device__ float g_V[(size_t)ROWS_K * HID];
__device__ float g_S[(size_t)BATCH * N1 * N2];   // scores, then probabilities in-place

// ---------------------------------------------------------------------------
// fast exp(x) for x <= 0 (softmax argument). Degree-6 polynomial for 2^f,
// exponent assembled via bit ops. Rel err < 3e-5, runs on FMA/ALU pipes
// instead of MUFU (67M exps would cost ~0.25ms on MUFU alone).
// ---------------------------------------------------------------------------
__device__ __forceinline__ float fast_exp_neg(float x) {
    float t = x * 1.4426950408889634f;      // x * log2(e)
    float n = floorf(t);
    float f = t - n;                        // f in [0,1)
    float p = 1.5404027e-4f;
    p = fmaf(p, f, 1.3333558e-3f);
    p = fmaf(p, f, 9.6181291e-3f);
    p = fmaf(p, f, 5.5504109e-2f);
    p = fmaf(p, f, 2.4022651e-1f);
    p = fmaf(p, f, 6.9314718e-1f);
    p = fmaf(p, f, 1.0f);
    int ni = (int)n;
    ni = max(ni, -126);                     // underflow clamp -> denormal-free
    return p * __int_as_float((ni + 127) << 23);
}

// ---------------------------------------------------------------------------
// Kernel 1: fused QKV projection.  C = X @ W + b
//   blockIdx.z: 0 -> Q(inputs1,Wq,bq), 1 -> K(inputs2,Wk,bk), 2 -> V(inputs2,Wv,bv)
//   X: (16384 x 256) row-major, W: (256 x 256) row-major, C: (16384 x 256)
// ---------------------------------------------------------------------------
__global__ __launch_bounds__(256, 2)
void gemm_proj(const float* __restrict__ x1, const float* __restrict__ x2,
               const float* __restrict__ Wq, const float* __restrict__ bq,
               const float* __restrict__ Wk, const float* __restrict__ bk,
               const float* __restrict__ Wv, const float* __restrict__ bv) {
    __shared__ __align__(16) float As[BKK][BM + PAD];
    __shared__ __align__(16) float Bs[BKK][BN + PAD];

    int z = blockIdx.z;
    const float* X    = (z == 0) ? x1 : x2;
    const float* W    = (z == 0) ? Wq : ((z == 1) ? Wk : Wv);
    const float* bias = (z == 0) ? bq : ((z == 1) ? bk : bv);
    float* C          = (z == 0) ? g_Q : ((z == 1) ? g_K : g_V);

    int rowBase = blockIdx.y * BM;
    int colBase = blockIdx.x * BN;
    int tid = threadIdx.x;
    int tx = tid & 15, ty = tid >> 4;
    int tm = ty * 8, tn = tx * 8;

    float acc[8][8];
    #pragma unroll
    for (int i = 0; i < 8; ++i)
        #pragma unroll
        for (int j = 0; j < 8; ++j) acc[i][j] = 0.f;

    for (int k0 = 0; k0 < DIM; k0 += BKK) {
        // A tile (128x16) transposed into As[k][m]
        #pragma unroll
        for (int p = 0; p < 2; ++p) {
            int lin = tid + p * 256;
            int r = lin >> 2, c4 = lin & 3;
            float4 v = *(const float4*)&X[(size_t)(rowBase + r) * DIM + k0 + c4 * 4];
            As[c4 * 4 + 0][r] = v.x; As[c4 * 4 + 1][r] = v.y;
            As[c4 * 4 + 2][r] = v.z; As[c4 * 4 + 3][r] = v.w;
        }
        // B tile (16x128) direct into Bs[k][n]
        #pragma unroll
        for (int p = 0; p < 2; ++p) {
            int lin = tid + p * 256;
            int r = lin >> 5, c4 = lin & 31;
            *(float4*)&Bs[r][c4 * 4] =
                *(const float4*)&W[(size_t)(k0 + r) * HID + colBase + c4 * 4];
        }
        __syncthreads();
        #pragma unroll
        for (int kk = 0; kk < BKK; ++kk) {
            float a[8], b[8];
            *(float4*)(a)     = *(const float4*)&As[kk][tm];
            *(float4*)(a + 4) = *(const float4*)&As[kk][tm + 4];
            *(float4*)(b)     = *(const float4*)&Bs[kk][tn];
            *(float4*)(b + 4) = *(const float4*)&Bs[kk][tn + 4];
            #pragma unroll
            for (int i = 0; i < 8; ++i)
                #pragma unroll
                for (int j = 0; j < 8; ++j)
                    acc[i][j] = fmaf(a[i], b[j], acc[i][j]);
        }
        __syncthreads();
    }

    float bb[8];
    #pragma unroll
    for (int j = 0; j < 8; ++j) bb[j] = bias[colBase + tn + j];
    #pragma unroll
    for (int i = 0; i < 8; ++i) {
        size_t off = (size_t)(rowBase + tm + i) * HID + colBase + tn;
        float4 o0, o1;
        o0.x = acc[i][0] + bb[0]; o0.y = acc[i][1] + bb[1];
        o0.z = acc[i][2] + bb[2]; o0.w = acc[i][3] + bb[3];
        o1.x = acc[i][4] + bb[4]; o1.y = acc[i][5] + bb[5];
        o1.z = acc[i][6] + bb[6]; o1.w = acc[i][7] + bb[7];
        *(float4*)&C[off]     = o0;
        *(float4*)&C[off + 4] = o1;
    }
}

// ---------------------------------------------------------------------------
// Kernel 2: S[b,i,j] = scale * sum_h Q[b,i,h] * K[b,j,h]
// ---------------------------------------------------------------------------
__global__ __launch_bounds__(256, 2)
void gemm_scores() {
    __shared__ __align__(16) float As[BKK][BM + PAD];
    __shared__ __align__(16) float Bs[BKK][BN + PAD];

    int b = blockIdx.z;
    const float* Q = g_Q + (size_t)b * N1 * HID;
    const float* K = g_K + (size_t)b * N2 * HID;
    float* S = g_S + (size_t)b * N1 * N2;

    int rowBase = blockIdx.y * BM;   // i
    int colBase = blockIdx.x * BN;   // j
    int tid = threadIdx.x;
    int tx = tid & 15, ty = tid >> 4;
    int tm = ty * 8, tn = tx * 8;

    float acc[8][8];
    #pragma unroll
    for (int i = 0; i < 8; ++i)
        #pragma unroll
        for (int j = 0; j < 8; ++j) acc[i][j] = 0.f;

    for (int k0 = 0; k0 < HID; k0 += BKK) {
        #pragma unroll
        for (int p = 0; p < 2; ++p) {
            int lin = tid + p * 256;
            int r = lin >> 2, c4 = lin & 3;
            float4 v = *(const float4*)&Q[(size_t)(rowBase + r) * HID + k0 + c4 * 4];
            As[c4 * 4 + 0][r] = v.x; As[c4 * 4 + 1][r] = v.y;
            As[c4 * 4 + 2][r] = v.z; As[c4 * 4 + 3][r] = v.w;
        }
        #pragma unroll
        for (int p = 0; p < 2; ++p) {
            int lin = tid + p * 256;
            int r = lin >> 2, c4 = lin & 3;
            float4 v = *(const float4*)&K[(size_t)(colBase + r) * HID + k0 + c4 * 4];
            Bs[c4 * 4 + 0][r] = v.x; Bs[c4 * 4 + 1][r] = v.y;
            Bs[c4 * 4 + 2][r] = v.z; Bs[c4 * 4 + 3][r] = v.w;
        }
        __syncthreads();
        #pragma unroll
        for (int kk = 0; kk < BKK; ++kk) {
            float a[8], bb[8];
            *(float4*)(a)      = *(const float4*)&As[kk][tm];
            *(float4*)(a + 4)  = *(const float4*)&As[kk][tm + 4];
            *(float4*)(bb)     = *(const float4*)&Bs[kk][tn];
            *(float4*)(bb + 4) = *(const float4*)&Bs[kk][tn + 4];
            #pragma unroll
            for (int i = 0; i < 8; ++i)
                #pragma unroll
                for (int j = 0; j < 8; ++j)
                    acc[i][j] = fmaf(a[i], bb[j], acc[i][j]);
        }
        __syncthreads();
    }

    const float scale = 0.0625f;   // 1/sqrt(256)
    #pragma unroll
    for (int i = 0; i < 8; ++i) {
        size_t off = (size_t)(rowBase + tm + i) * N2 + colBase + tn;
        float4 o0, o1;
        o0.x = acc[i][0] * scale; o0.y = acc[i][1] * scale;
        o0.z = acc[i][2] * scale; o0.w = acc[i][3] * scale;
        o1.x = acc[i][4] * scale; o1.y = acc[i][5] * scale;
        o1.z = acc[i][6] * scale; o1.w = acc[i][7] * scale;
        *(float4*)&S[off]     = o0;
        *(float4*)&S[off + 4] = o1;
    }
}

// ---------------------------------------------------------------------------
// Kernel 3: per-row masked softmax, in place in g_S.
//   v = mask>0 ? s : 1e-9 ;  p = exp(v - max) / sum
// One block (256 threads) per row of 4096; values cached in 16 regs/thread.
// ---------------------------------------------------------------------------
__global__ __launch_bounds__(256)
void softmax_mask(const int* __restrict__ mask) {
    size_t row = blockIdx.x;
    float* srow = g_S + row * (size_t)N2;
    const int* mrow = mask + row * (size_t)N2;

    float v[16];
    float m = -1e30f;
    #pragma unroll
    for (int t = 0; t < 16; ++t) {
        int j = threadIdx.x + t * 256;
        float s = srow[j];
        int mk = mrow[j];
        float val = (mk > 0) ? s : 1e-9f;
        v[t] = val;
        m = fmaxf(m, val);
    }
    // block max
    #pragma unroll
    for (int o = 16; o > 0; o >>= 1) m = fmaxf(m, __shfl_xor_sync(~0u, m, o));
    __shared__ float redM[8];
    __shared__ float redS[8];
    int lane = threadIdx.x & 31, w = threadIdx.x >> 5;
    if (lane == 0) redM[w] = m;
    __syncthreads();
    float mAll = redM[0];
    #pragma unroll
    for (int i = 1; i < 8; ++i) mAll = fmaxf(mAll, redM[i]);

    float sum = 0.f;
    #pragma unroll
    for (int t = 0; t < 16; ++t) {
        float p = fast_exp_neg(v[t] - mAll);
        v[t] = p;
        sum += p;
    }
    #pragma unroll
    for (int o = 16; o > 0; o >>= 1) sum += __shfl_xor_sync(~0u, sum, o);
    if (lane == 0) redS[w] = sum;
    __syncthreads();
    float sAll = 0.f;
    #pragma unroll
    for (int i = 0; i < 8; ++i) sAll += redS[i];
    float inv = 1.0f / sAll;

    #pragma unroll
    for (int t = 0; t < 16; ++t)
        srow[threadIdx.x + t * 256] = v[t] * inv;
}

// ---------------------------------------------------------------------------
// Kernel 4: O[b,i,c] = sum_j P[b,i,j] * V[b,j,c]
// ---------------------------------------------------------------------------
__global__ __launch_bounds__(256, 2)
void gemm_pv(float* __restrict__ out) {
    __shared__ __align__(16) float As[BKK][BM + PAD];
    __shared__ __align__(16) float Bs[BKK][BN + PAD];

    int b = blockIdx.z;
    const float* P = g_S + (size_t)b * N1 * N2;
    const float* V = g_V + (size_t)b * N2 * HID;
    float* O = out + (size_t)b * N1 * HID;

    int rowBase = blockIdx.y * BM;   // i
    int colBase = blockIdx.x * BN;   // c
    int tid = threadIdx.x;
    int tx = tid & 15, ty = tid >> 4;
    int tm = ty * 8, tn = tx * 8;

    float acc[8][8];
    #pragma unroll
    for (int i = 0; i < 8; ++i)
        #pragma unroll
        for (int j = 0; j < 8; ++j) acc[i][j] = 0.f;

    for (int k0 = 0; k0 < N2; k0 += BKK) {
        // P tile (128 x 16), lda = N2, transposed store
        #pragma unroll
        for (int p = 0; p < 2; ++p) {
            int lin = tid + p * 256;
            int r = lin >> 2, c4 = lin & 3;
            float4 v = *(const float4*)&P[(size_t)(rowBase + r) * N2 + k0 + c4 * 4];
            As[c4 * 4 + 0][r] = v.x; As[c4 * 4 + 1][r] = v.y;
            As[c4 * 4 + 2][r] = v.z; As[c4 * 4 + 3][r] = v.w;
        }
        // V tile (16 x 128), ldb = HID, direct store
        #pragma unroll
        for (int p = 0; p < 2; ++p) {
            int lin = tid + p * 256;
            int r = lin >> 5, c4 = lin & 31;
            *(float4*)&Bs[r][c4 * 4] =
                *(const float4*)&V[(size_t)(k0 + r) * HID + colBase + c4 * 4];
        }
        __syncthreads();
        #pragma unroll
        for (int kk = 0; kk < BKK; ++kk) {
            float a[8], bb[8];
            *(float4*)(a)      = *(const float4*)&As[kk][tm];
            *(float4*)(a + 4)  = *(const float4*)&As[kk][tm + 4];
            *(float4*)(bb)     = *(const float4*)&Bs[kk][tn];
            *(float4*)(bb + 4) = *(const float4*)&Bs[kk][tn + 4];
            #pragma unroll
            for (int i = 0; i < 8; ++i)
                #pragma unroll
                for (int j = 0; j < 8; ++j)
                    acc[i][j] = fmaf(a[i], bb[j], acc[i][j]);
        }
        __syncthreads();
    }

    #pragma unroll
    for (int i = 0; i < 8; ++i) {
        size_t off = (size_t)(rowBase + tm + i) * HID + colBase + tn;
        *(float4*)&O[off]     = *(float4*)&acc[i][0];
        *(float4*)&O[off + 4] = *(float4*)&acc[i][4];
    }
}

// ---------------------------------------------------------------------------
extern "C" void kernel_launch(void* const* d_in, const int* in_sizes, int n_in,
                              void* d_out, int out_size) {
    const float* x1  = (const float*)d_in[0];
    const float* x2  = (const float*)d_in[1];
    const int*   msk = (const int*)  d_in[2];
    const float* Wq  = (const float*)d_in[3];
    const float* bq  = (const float*)d_in[4];
    const float* Wk  = (const float*)d_in[5];
    const float* bk  = (const float*)d_in[6];
    const float* Wv  = (const float*)d_in[7];
    const float* bv  = (const float*)d_in[8];
    float* out = (float*)d_out;

    dim3 blk(256);
    gemm_proj  <<<dim3(HID / BN, ROWS_Q / BM, 3), blk>>>(x1, x2, Wq, bq, Wk, bk, Wv, bv);
    gemm_scores<<<dim3(N2 / BN, N1 / BM, BATCH), blk>>>();
    softmax_mask<<<dim3(BATCH * N1), blk>>>(msk);
    gemm_pv    <<<dim3(HID / BN, N1 / BM, BATCH), blk>>>(out);
}

// round 3
// speedup vs baseline: 2.1636x; 2.1636x over previous
#include <cuda_runtime.h>
#include <cuda_bf16.h>
#include <cstdint>
#include <cstddef>

#define BATCH 4
#define NSEQ  4096
#define DHID  256
#define ROWS  16384            // BATCH * NSEQ

#define BM 128
#define BN 128
#define KC 32                  // K elements per pipeline chunk
#define TILE_BYTES 8192        // 128 rows * 32 bf16 * 2B
#define STAGE_BYTES (4 * TILE_BYTES)
#define SMEM_SZ (2 * STAGE_BYTES)   // 64 KB

// ---------------- device scratch (split-bf16 hi/lo planes) ----------------
__device__ __align__(16) __nv_bfloat16 g_Xh[(size_t)2 * ROWS * DHID];
__device__ __align__(16) __nv_bfloat16 g_Xl[(size_t)2 * ROWS * DHID];
__device__ __align__(16) __nv_bfloat16 g_Wth[3 * DHID * DHID];
__device__ __align__(16) __nv_bfloat16 g_Wtl[3 * DHID * DHID];
__device__ __align__(16) __nv_bfloat16 g_Qh[(size_t)ROWS * DHID];
__device__ __align__(16) __nv_bfloat16 g_Ql[(size_t)ROWS * DHID];
__device__ __align__(16) __nv_bfloat16 g_Kh[(size_t)ROWS * DHID];
__device__ __align__(16) __nv_bfloat16 g_Kl[(size_t)ROWS * DHID];
__device__ __align__(16) __nv_bfloat16 g_Vth[(size_t)BATCH * DHID * NSEQ];
__device__ __align__(16) __nv_bfloat16 g_Vtl[(size_t)BATCH * DHID * NSEQ];
__device__ __align__(16) float         g_S  [(size_t)ROWS * NSEQ];
__device__ __align__(16) __nv_bfloat16 g_Ph[(size_t)ROWS * NSEQ];
__device__ __align__(16) __nv_bfloat16 g_Pl[(size_t)ROWS * NSEQ];

// ---------------- PTX helpers (arch-generic only; no tcgen05) --------------
__device__ __forceinline__ uint32_t smem_u32(const void* p) {
    uint32_t a;
    asm("{ .reg .u64 t; cvta.to.shared.u64 t, %1; cvt.u32.u64 %0, t; }" : "=r"(a) : "l"(p));
    return a;
}
__device__ __forceinline__ uint32_t sw64(uint32_t b) { return b ^ ((b >> 3) & 0x30); }

__device__ __forceinline__ void cpa16(uint32_t dst, const void* src) {
    asm volatile("cp.async.cg.shared.global [%0], [%1], 16;" :: "r"(dst), "l"(src));
}
__device__ __forceinline__ void cp_commit() { asm volatile("cp.async.commit_group;"); }
template<int N> __device__ __forceinline__ void cp_wait() {
    asm volatile("cp.async.wait_group %0;" :: "n"(N));
}
__device__ __forceinline__ void ldm_x4(uint32_t* d, uint32_t a) {
    asm volatile("ldmatrix.sync.aligned.m8n8.x4.shared.b16 {%0,%1,%2,%3}, [%4];"
                 : "=r"(d[0]), "=r"(d[1]), "=r"(d[2]), "=r"(d[3]) : "r"(a));
}
__device__ __forceinline__ void ldm_x2(uint32_t* d, uint32_t a) {
    asm volatile("ldmatrix.sync.aligned.m8n8.x2.shared.b16 {%0,%1}, [%2];"
                 : "=r"(d[0]), "=r"(d[1]) : "r"(a));
}
__device__ __forceinline__ void mma16816(float* d, const uint32_t* a, const uint32_t* b) {
    asm volatile("mma.sync.aligned.m16n8k16.row.col.f32.bf16.bf16.f32 "
                 "{%0,%1,%2,%3}, {%4,%5,%6,%7}, {%8,%9}, {%0,%1,%2,%3};"
                 : "+f"(d[0]), "+f"(d[1]), "+f"(d[2]), "+f"(d[3])
                 : "r"(a[0]), "r"(a[1]), "r"(a[2]), "r"(a[3]), "r"(b[0]), "r"(b[1]));
}

__device__ __forceinline__ void split2(float f, __nv_bfloat16& h, __nv_bfloat16& l) {
    h = __float2bfloat16(f);
    l = __float2bfloat16(f - __bfloat162float(h));
}
__device__ __forceinline__ uint32_t pack2(__nv_bfloat16 a, __nv_bfloat16 b) {
    return (uint32_t)__bfloat16_as_ushort(a) | ((uint32_t)__bfloat16_as_ushort(b) << 16);
}

// ---------------- shared GEMM machinery ------------------------------------
struct GemmPtrs {
    const __nv_bfloat16 *Ah, *Al, *Bh, *Bl;
    size_t lda, ldb;
};

__device__ __forceinline__ void prefetch_stage(const GemmPtrs& g, int c, int s,
                                               uint32_t sbase, int tid) {
    size_t aoff = (size_t)(tid >> 1) * g.lda + (size_t)c * KC;
    size_t boff = (size_t)(tid >> 1) * g.ldb + (size_t)c * KC;
    int bo = (tid & 1) * 32;
    uint32_t rowb = (uint32_t)(tid >> 1) * 64 + bo;
    uint32_t stb = sbase + s * STAGE_BYTES;
    const char* pah = (const char*)(g.Ah + aoff) + bo;
    const char* pal = (const char*)(g.Al + aoff) + bo;
    const char* pbh = (const char*)(g.Bh + boff) + bo;
    const char* pbl = (const char*)(g.Bl + boff) + bo;
    #pragma unroll
    for (int j = 0; j < 2; ++j) {
        uint32_t d = sw64(rowb + j * 16);
        cpa16(stb + d,                  pah + j * 16);
        cpa16(stb + TILE_BYTES + d,     pal + j * 16);
        cpa16(stb + 2 * TILE_BYTES + d, pbh + j * 16);
        cpa16(stb + 3 * TILE_BYTES + d, pbl + j * 16);
    }
    cp_commit();
}

__device__ __forceinline__ void compute_stage(uint32_t stb, int wm, int wn, int lane,
                                              float acc[4][4][4]) {
    #pragma unroll
    for (int ks = 0; ks < 2; ++ks) {
        uint32_t ah[4][4], al[4][4];
        int am  = (lane & 7) + ((lane >> 3) & 1) * 8;
        int akb = ks * 32 + (lane >> 4) * 16;
        #pragma unroll
        for (int mt = 0; mt < 4; ++mt) {
            uint32_t off = (uint32_t)(wm + mt * 16 + am) * 64 + akb;
            uint32_t sws = sw64(off);
            ldm_x4(ah[mt], stb + sws);
            ldm_x4(al[mt], stb + TILE_BYTES + sws);
        }
        uint32_t bh[4][2], bl[4][2];
        int l16 = lane & 15;
        int bn  = l16 & 7;
        int bkb = ks * 32 + (l16 >> 3) * 16;
        #pragma unroll
        for (int nt = 0; nt < 4; ++nt) {
            uint32_t off = (uint32_t)(wn + nt * 8 + bn) * 64 + bkb;
            uint32_t sws = sw64(off);
            ldm_x2(bh[nt], stb + 2 * TILE_BYTES + sws);
            ldm_x2(bl[nt], stb + 3 * TILE_BYTES + sws);
        }
        #pragma unroll
        for (int mt = 0; mt < 4; ++mt)
            #pragma unroll
            for (int nt = 0; nt < 4; ++nt) {
                mma16816(acc[mt][nt], ah[mt], bh[nt]);
                mma16816(acc[mt][nt], ah[mt], bl[nt]);
                mma16816(acc[mt][nt], al[mt], bh[nt]);
            }
    }
}

__device__ __forceinline__ void gemm_main(const GemmPtrs& g, int nchunks, char* smem,
                                          float acc[4][4][4]) {
    int tid = threadIdx.x, lane = tid & 31, warp = tid >> 5;
    int wm = (warp >> 2) * 64, wn = (warp & 3) * 32;
    uint32_t sbase = smem_u32(smem);
    prefetch_stage(g, 0, 0, sbase, tid);
    for (int c = 0; c < nchunks; ++c) {
        int s = c & 1;
        if (c + 1 < nchunks) { prefetch_stage(g, c + 1, s ^ 1, sbase, tid); cp_wait<1>(); }
        else                 { cp_wait<0>(); }
        __syncthreads();
        compute_stage(sbase + s * STAGE_BYTES, wm, wn, lane, acc);
        __syncthreads();
    }
}

// ---------------- prep kernels ---------------------------------------------
__global__ __launch_bounds__(256)
void k_prep_x(const float* __restrict__ x1, const float* __restrict__ x2) {
    size_t i = ((size_t)blockIdx.x * 256 + threadIdx.x) * 4;
    const size_t half = (size_t)ROWS * DHID;
    const float* src = (i < half) ? (x1 + i) : (x2 + (i - half));
    float4 v = *(const float4*)src;
    __nv_bfloat16 h0, l0, h1, l1, h2, l2, h3, l3;
    split2(v.x, h0, l0); split2(v.y, h1, l1);
    split2(v.z, h2, l2); split2(v.w, h3, l3);
    uint2 hp = make_uint2(pack2(h0, h1), pack2(h2, h3));
    uint2 lp = make_uint2(pack2(l0, l1), pack2(l2, l3));
    *(uint2*)(g_Xh + i) = hp;
    *(uint2*)(g_Xl + i) = lp;
}

__global__ void k_prep_w(const float* __restrict__ Wq, const float* __restrict__ Wk,
                         const float* __restrict__ Wv) {
    __shared__ float t[32][33];
    int z = blockIdx.z;
    const float* W = (z == 0) ? Wq : ((z == 1) ? Wk : Wv);
    int n0 = blockIdx.x * 32, d0 = blockIdx.y * 32;
    int tx = threadIdx.x, ty = threadIdx.y;           // block (32,8)
    #pragma unroll
    for (int i = 0; i < 4; ++i)
        t[ty + i * 8][tx] = W[(size_t)(d0 + ty + i * 8) * DHID + n0 + tx];
    __syncthreads();
    #pragma unroll
    for (int i = 0; i < 4; ++i) {
        float f = t[tx][ty + i * 8];                  // = W[d0+tx][n0+ty+i*8]
        __nv_bfloat16 h, l; split2(f, h, l);
        size_t o = (size_t)z * DHID * DHID + (size_t)(n0 + ty + i * 8) * DHID + d0 + tx;
        g_Wth[o] = h; g_Wtl[o] = l;
    }
}

// ---------------- GEMM kernels ---------------------------------------------
__global__ __launch_bounds__(256)
void k_proj(const float* __restrict__ bq, const float* __restrict__ bk,
            const float* __restrict__ bv) {
    extern __shared__ char smem[];
    int z = blockIdx.z;
    int rowBase = blockIdx.y * BM, colBase = blockIdx.x * BN;
    size_t arow = ((z == 0) ? 0 : (size_t)ROWS) + rowBase;
    GemmPtrs g;
    g.Ah = g_Xh + arow * DHID;  g.Al = g_Xl + arow * DHID;
    size_t wo = (size_t)z * DHID * DHID + (size_t)colBase * DHID;
    g.Bh = g_Wth + wo;          g.Bl = g_Wtl + wo;
    g.lda = DHID; g.ldb = DHID;

    float acc[4][4][4];
    #pragma unroll
    for (int a = 0; a < 4; ++a)
        #pragma unroll
        for (int b = 0; b < 4; ++b)
            #pragma unroll
            for (int c = 0; c < 4; ++c) acc[a][b][c] = 0.f;

    gemm_main(g, DHID / KC, smem, acc);

    const float* bias = (z == 0) ? bq : ((z == 1) ? bk : bv);
    int lane = threadIdx.x & 31, warp = threadIdx.x >> 5;
    int wm = (warp >> 2) * 64, wn = (warp & 3) * 32;
    int rl = lane >> 2, cl = (lane & 3) * 2;
    #pragma unroll
    for (int mt = 0; mt < 4; ++mt)
        #pragma unroll
        for (int nt = 0; nt < 4; ++nt) {
            int col = colBase + wn + nt * 8 + cl;
            float b0 = bias[col], b1 = bias[col + 1];
            #pragma unroll
            for (int h = 0; h < 2; ++h) {
                int r = rowBase + wm + mt * 16 + rl + h * 8;
                float v0 = acc[mt][nt][h * 2 + 0] + b0;
                float v1 = acc[mt][nt][h * 2 + 1] + b1;
                __nv_bfloat16 h0, l0, h1, l1;
                split2(v0, h0, l0); split2(v1, h1, l1);
                if (z < 2) {
                    __nv_bfloat16* dh = (z == 0) ? g_Qh : g_Kh;
                    __nv_bfloat16* dl = (z == 0) ? g_Ql : g_Kl;
                    *(uint32_t*)&dh[(size_t)r * DHID + col] = pack2(h0, h1);
                    *(uint32_t*)&dl[(size_t)r * DHID + col] = pack2(l0, l1);
                } else {
                    int bb = r >> 12, j = r & 4095;
                    size_t o0 = ((size_t)(bb * DHID + col)) * NSEQ + j;
                    g_Vth[o0] = h0;        g_Vtl[o0] = l0;
                    g_Vth[o0 + NSEQ] = h1; g_Vtl[o0 + NSEQ] = l1;
                }
            }
        }
}

__global__ __launch_bounds__(256)
void k_scores() {
    extern __shared__ char smem[];
    int bz = blockIdx.z;
    int rowBase = blockIdx.y * BM, colBase = blockIdx.x * BN;
    GemmPtrs g;
    size_t ao = ((size_t)bz * NSEQ + rowBase) * DHID;
    size_t bo = ((size_t)bz * NSEQ + colBase) * DHID;
    g.Ah = g_Qh + ao; g.Al = g_Ql + ao;
    g.Bh = g_Kh + bo; g.Bl = g_Kl + bo;
    g.lda = DHID; g.ldb = DHID;

    float acc[4][4][4];
    #pragma unroll
    for (int a = 0; a < 4; ++a)
        #pragma unroll
        for (int b = 0; b < 4; ++b)
            #pragma unroll
            for (int c = 0; c < 4; ++c) acc[a][b][c] = 0.f;

    gemm_main(g, DHID / KC, smem, acc);

    int lane = threadIdx.x & 31, warp = threadIdx.x >> 5;
    int wm = (warp >> 2) * 64, wn = (warp & 3) * 32;
    int rl = lane >> 2, cl = (lane & 3) * 2;
    const float scale = 0.0625f;
    #pragma unroll
    for (int mt = 0; mt < 4; ++mt)
        #pragma unroll
        for (int nt = 0; nt < 4; ++nt) {
            int col = colBase + wn + nt * 8 + cl;
            #pragma unroll
            for (int h = 0; h < 2; ++h) {
                int r = rowBase + wm + mt * 16 + rl + h * 8;
                float2 o;
                o.x = acc[mt][nt][h * 2 + 0] * scale;
                o.y = acc[mt][nt][h * 2 + 1] * scale;
                *(float2*)&g_S[((size_t)bz * NSEQ + r) * NSEQ + col] = o;
            }
        }
}

__global__ __launch_bounds__(256)
void k_pv(float* __restrict__ out) {
    extern __shared__ char smem[];
    int bz = blockIdx.z;
    int rowBase = blockIdx.y * BM, colBase = blockIdx.x * BN;
    GemmPtrs g;
    size_t ao = ((size_t)bz * NSEQ + rowBase) * NSEQ;
    size_t bo = ((size_t)bz * DHID + colBase) * NSEQ;
    g.Ah = g_Ph + ao; g.Al = g_Pl + ao;
    g.Bh = g_Vth + bo; g.Bl = g_Vtl + bo;
    g.lda = NSEQ; g.ldb = NSEQ;

    float acc[4][4][4];
    #pragma unroll
    for (int a = 0; a < 4; ++a)
        #pragma unroll
        for (int b = 0; b < 4; ++b)
            #pragma unroll
            for (int c = 0; c < 4; ++c) acc[a][b][c] = 0.f;

    gemm_main(g, NSEQ / KC, smem, acc);

    int lane = threadIdx.x & 31, warp = threadIdx.x >> 5;
    int wm = (warp >> 2) * 64, wn = (warp & 3) * 32;
    int rl = lane >> 2, cl = (lane & 3) * 2;
    #pragma unroll
    for (int mt = 0; mt < 4; ++mt)
        #pragma unroll
        for (int nt = 0; nt < 4; ++nt) {
            int col = colBase + wn + nt * 8 + cl;
            #pragma unroll
            for (int h = 0; h < 2; ++h) {
                int r = rowBase + wm + mt * 16 + rl + h * 8;
                float2 o;
                o.x = acc[mt][nt][h * 2 + 0];
                o.y = acc[mt][nt][h * 2 + 1];
                *(float2*)&out[((size_t)bz * NSEQ + r) * DHID + col] = o;
            }
        }
}

// ---------------- softmax ---------------------------------------------------
__device__ __forceinline__ float fast_exp_neg(float x) {
    float t = x * 1.4426950408889634f;
    float n = floorf(t);
    float f = t - n;
    float p = 1.5404027e-4f;
    p = fmaf(p, f, 1.3333558e-3f);
    p = fmaf(p, f, 9.6181291e-3f);
    p = fmaf(p, f, 5.5504109e-2f);
    p = fmaf(p, f, 2.4022651e-1f);
    p = fmaf(p, f, 6.9314718e-1f);
    p = fmaf(p, f, 1.0f);
    int ni = (int)n;
    ni = max(ni, -126);
    return p * __int_as_float((ni + 127) << 23);
}

__global__ __launch_bounds__(256)
void k_softmax(const int* __restrict__ mask) {
    size_t row = blockIdx.x;
    const float2* srow = (const float2*)(g_S + row * NSEQ);
    const int2*   mrow = (const int2*)(mask + row * NSEQ);
    uint32_t* ph = (uint32_t*)(g_Ph + row * NSEQ);
    uint32_t* pl = (uint32_t*)(g_Pl + row * NSEQ);
    int tid = threadIdx.x;

    float2 v[8];
    float m = -1e30f;
    #pragma unroll
    for (int t = 0; t < 8; ++t) {
        int j = tid + t * 256;
        float2 s = srow[j];
        int2  mk = mrow[j];
        s.x = (mk.x > 0) ? s.x : 1e-9f;
        s.y = (mk.y > 0) ? s.y : 1e-9f;
        v[t] = s;
        m = fmaxf(m, fmaxf(s.x, s.y));
    }
    #pragma unroll
    for (int o = 16; o > 0; o >>= 1) m = fmaxf(m, __shfl_xor_sync(~0u, m, o));
    __shared__ float redM[8], redS[8];
    int lane = tid & 31, w = tid >> 5;
    if (lane == 0) redM[w] = m;
    __syncthreads();
    float mAll = redM[0];
    #pragma unroll
    for (int i = 1; i < 8; ++i) mAll = fmaxf(mAll, redM[i]);

    float sum = 0.f;
    #pragma unroll
    for (int t = 0; t < 8; ++t) {
        v[t].x = fast_exp_neg(v[t].x - mAll);
        v[t].y = fast_exp_neg(v[t].y - mAll);
        sum += v[t].x + v[t].y;
    }
    #pragma unroll
    for (int o = 16; o > 0; o >>= 1) sum += __shfl_xor_sync(~0u, sum, o);
    if (lane == 0) redS[w] = sum;
    __syncthreads();
    float sAll = 0.f;
    #pragma unroll
    for (int i = 0; i < 8; ++i) sAll += redS[i];
    float inv = 1.0f / sAll;

    #pragma unroll
    for (int t = 0; t < 8; ++t) {
        int j = tid + t * 256;
        __nv_bfloat16 h0, l0, h1, l1;
        split2(v[t].x * inv, h0, l0);
        split2(v[t].y * inv, h1, l1);
        ph[j] = pack2(h0, h1);
        pl[j] = pack2(l0, l1);
    }
}

// ---------------------------------------------------------------------------
extern "C" void kernel_launch(void* const* d_in, const int* in_sizes, int n_in,
                              void* d_out, int out_size) {
    const float* x1  = (const float*)d_in[0];
    const float* x2  = (const float*)d_in[1];
    const int*   msk = (const int*)  d_in[2];
    const float* Wq  = (const float*)d_in[3];
    const float* bq  = (const float*)d_in[4];
    const float* Wk  = (const float*)d_in[5];
    const float* bk  = (const float*)d_in[6];
    const float* Wv  = (const float*)d_in[7];
    const float* bv  = (const float*)d_in[8];
    float* out = (float*)d_out;

    cudaFuncSetAttribute(k_proj,   cudaFuncAttributeMaxDynamicSharedMemorySize, SMEM_SZ);
    cudaFuncSetAttribute(k_scores, cudaFuncAttributeMaxDynamicSharedMemorySize, SMEM_SZ);
    cudaFuncSetAttribute(k_pv,     cudaFuncAttributeMaxDynamicSharedMemorySize, SMEM_SZ);

    k_prep_x <<<8192, 256>>>(x1, x2);
    k_prep_w <<<dim3(8, 8, 3), dim3(32, 8)>>>(Wq, Wk, Wv);
    k_proj   <<<dim3(2, 128, 3), 256, SMEM_SZ>>>(bq, bk, bv);
    k_scores <<<dim3(32, 32, 4), 256, SMEM_SZ>>>();
    k_softmax<<<ROWS, 256>>>(msk);
    k_pv     <<<dim3(2, 32, 4), 256, SMEM_SZ>>>(out);
}